// round 1
// baseline (speedup 1.0000x reference)
#include <cuda_runtime.h>
#include <math.h>

// Problem dims (fixed)
#define T_DIM   512
#define B_DIM   64
#define IN_DIM  512
#define H_DIM   1024
#define OUT_DIM 512
#define M_DIM   (T_DIM * B_DIM)   // 32768 rows for all GEMMs
#define G3H     (3 * H_DIM)       // 3072

// Scratch (static device allocations — allowed; no cudaMalloc anywhere)
__device__ float g_G[(size_t)M_DIM * G3H];     // gate buffer (reused both layers)
__device__ float g_Hbuf[(size_t)M_DIM * H_DIM]; // layer output buffer (reused)

// ---------------------------------------------------------------------------
// SGEMM: C = A(MxK, row-major) @ B(KxN, row-major) + bias[n]
// 128x128 tile, BK=16, 256 threads, 8x8 per-thread microtile.
// M % 128 == 0, N % 128 == 0, K % 16 == 0 (holds for all three calls).
// ---------------------------------------------------------------------------
#define BM 128
#define BN 128
#define BK 16
#define TM 8
#define TN 8

__global__ __launch_bounds__(256, 2)
void sgemm_bias_kernel(int M, int N, int K,
                       const float* __restrict__ A,
                       const float* __restrict__ B,
                       const float* __restrict__ bias,
                       float* __restrict__ C)
{
    __shared__ float As[BK][BM];      // transposed A tile
    __shared__ float Bs[BK][BN];

    const int tid  = threadIdx.x;
    const int cRow = blockIdx.y;      // M tile index
    const int cCol = blockIdx.x;      // N tile index

    const float* Ab = A + (size_t)cRow * BM * K;
    const float* Bb = B + (size_t)cCol * BN;
    float*       Cb = C + (size_t)cRow * BM * N + (size_t)cCol * BN;

    // per-thread output tile coords
    const int tCol = (tid % (BN / TN)) * TN;   // 0..120
    const int tRow = (tid / (BN / TN)) * TM;   // 0..120

    // A-load mapping: tile is BM x BK = 128x16 -> 512 float4, 2 per thread
    const int aRow  = tid / 4;        // 0..63 (and +64)
    const int aCol4 = tid % 4;        // which float4 within a 16-float row
    // B-load mapping: tile is BK x BN = 16x128 -> 512 float4, 2 per thread
    const int bRow  = tid / 32;       // 0..7 (and +8)
    const int bCol4 = tid % 32;

    float acc[TM][TN];
    #pragma unroll
    for (int i = 0; i < TM; i++)
        #pragma unroll
        for (int j = 0; j < TN; j++) acc[i][j] = 0.f;

    float ra[TM], rb[TN];

    for (int k0 = 0; k0 < K; k0 += BK) {
        // load A tile (transpose into As[k][m])
        #pragma unroll
        for (int i = 0; i < 2; i++) {
            const int r = aRow + i * 64;
            float4 v = *(const float4*)(Ab + (size_t)r * K + k0 + aCol4 * 4);
            As[aCol4 * 4 + 0][r] = v.x;
            As[aCol4 * 4 + 1][r] = v.y;
            As[aCol4 * 4 + 2][r] = v.z;
            As[aCol4 * 4 + 3][r] = v.w;
        }
        // load B tile
        #pragma unroll
        for (int i = 0; i < 2; i++) {
            const int r = bRow + i * 8;
            *(float4*)(&Bs[r][bCol4 * 4]) =
                *(const float4*)(Bb + (size_t)(k0 + r) * N + bCol4 * 4);
        }
        __syncthreads();

        #pragma unroll
        for (int k = 0; k < BK; k++) {
            #pragma unroll
            for (int i = 0; i < TM; i += 4) {
                float4 v = *(const float4*)(&As[k][tRow + i]);
                ra[i+0] = v.x; ra[i+1] = v.y; ra[i+2] = v.z; ra[i+3] = v.w;
            }
            #pragma unroll
            for (int j = 0; j < TN; j += 4) {
                float4 v = *(const float4*)(&Bs[k][tCol + j]);
                rb[j+0] = v.x; rb[j+1] = v.y; rb[j+2] = v.z; rb[j+3] = v.w;
            }
            #pragma unroll
            for (int i = 0; i < TM; i++)
                #pragma unroll
                for (int j = 0; j < TN; j++)
                    acc[i][j] += ra[i] * rb[j];
        }
        __syncthreads();
    }

    // epilogue: + bias, vectorized store
    #pragma unroll
    for (int i = 0; i < TM; i++) {
        #pragma unroll
        for (int j = 0; j < TN; j += 4) {
            const float* bp = bias + (size_t)cCol * BN + tCol + j;
            float4 v;
            v.x = acc[i][j+0] + bp[0];
            v.y = acc[i][j+1] + bp[1];
            v.z = acc[i][j+2] + bp[2];
            v.w = acc[i][j+3] + bp[3];
            *(float4*)(Cb + (size_t)(tRow + i) * N + tCol + j) = v;
        }
    }
}

// ---------------------------------------------------------------------------
// Activation: in-place on G (M x 3H). For each (m, h):
//   z slot <- (1 - sigmoid(f)) * tanh(z)     (the scan additive term 'a')
//   f slot <- sigmoid(f)
//   o slot <- sigmoid(o)
// Vectorized float4 over h.
// ---------------------------------------------------------------------------
__device__ __forceinline__ float sigmoidf_(float x) {
    return 1.0f / (1.0f + expf(-x));
}

__global__ void qrnn_act_kernel(float* __restrict__ G)
{
    // total vec elements: M * (H/4)
    const int HV = H_DIM / 4;
    int v = blockIdx.x * blockDim.x + threadIdx.x;
    if (v >= M_DIM * HV) return;
    const int m  = v / HV;
    const int hv = v % HV;
    const size_t base = (size_t)m * G3H + (size_t)hv * 4;

    float4 z = *(float4*)(G + base);
    float4 f = *(float4*)(G + base + H_DIM);
    float4 o = *(float4*)(G + base + 2 * H_DIM);

    float4 fs, a, os;
    fs.x = sigmoidf_(f.x); fs.y = sigmoidf_(f.y);
    fs.z = sigmoidf_(f.z); fs.w = sigmoidf_(f.w);
    a.x = (1.0f - fs.x) * tanhf(z.x);
    a.y = (1.0f - fs.y) * tanhf(z.y);
    a.z = (1.0f - fs.z) * tanhf(z.z);
    a.w = (1.0f - fs.w) * tanhf(z.w);
    os.x = sigmoidf_(o.x); os.y = sigmoidf_(o.y);
    os.z = sigmoidf_(o.z); os.w = sigmoidf_(o.w);

    *(float4*)(G + base)             = a;
    *(float4*)(G + base + H_DIM)     = fs;
    *(float4*)(G + base + 2 * H_DIM) = os;
}

// ---------------------------------------------------------------------------
// fo-pool scan: one thread per (b, h) lane, sequential over T.
//   c_t = f_t * c_{t-1} + a_t ;  Hout_t = o_t * c_t
// Streaming, coalesced across h.
// ---------------------------------------------------------------------------
__global__ void qrnn_scan_kernel(const float* __restrict__ G,
                                 float* __restrict__ Hout)
{
    const int idx = blockIdx.x * blockDim.x + threadIdx.x;
    if (idx >= B_DIM * H_DIM) return;
    const int b = idx / H_DIM;
    const int h = idx % H_DIM;

    float c = 0.0f;
    #pragma unroll 4
    for (int t = 0; t < T_DIM; t++) {
        const size_t base = ((size_t)t * B_DIM + b) * G3H + h;
        const float a = G[base];
        const float f = G[base + H_DIM];
        const float o = G[base + 2 * H_DIM];
        c = fmaf(f, c, a);
        Hout[((size_t)t * B_DIM + b) * H_DIM + h] = o * c;
    }
}

// ---------------------------------------------------------------------------
// Launch: GEMM0 -> act -> scan -> GEMM1 -> act -> scan -> GEMM_fc
// Inputs (metadata order): x, W0, b0, W1, b1, Wfc, bfc
// ---------------------------------------------------------------------------
extern "C" void kernel_launch(void* const* d_in, const int* in_sizes, int n_in,
                              void* d_out, int out_size)
{
    const float* x   = (const float*)d_in[0];
    const float* W0  = (const float*)d_in[1];
    const float* b0  = (const float*)d_in[2];
    const float* W1  = (const float*)d_in[3];
    const float* b1  = (const float*)d_in[4];
    const float* Wfc = (const float*)d_in[5];
    const float* bfc = (const float*)d_in[6];
    float* out = (float*)d_out;

    float* G; float* Hb;
    cudaGetSymbolAddress((void**)&G,  g_G);
    cudaGetSymbolAddress((void**)&Hb, g_Hbuf);

    dim3 blk(256);
    dim3 grid_g0(G3H / BN, M_DIM / BM);      // 24 x 256
    dim3 grid_fc(OUT_DIM / BN, M_DIM / BM);  // 4 x 256

    const int actThreads = M_DIM * (H_DIM / 4);
    dim3 grid_act((actThreads + 255) / 256);
    dim3 grid_scan((B_DIM * H_DIM + 255) / 256);

    // Layer 0
    sgemm_bias_kernel<<<grid_g0, blk>>>(M_DIM, G3H, IN_DIM, x, W0, b0, G);
    qrnn_act_kernel<<<grid_act, blk>>>(G);
    qrnn_scan_kernel<<<grid_scan, blk>>>(G, Hb);

    // Layer 1
    sgemm_bias_kernel<<<grid_g0, blk>>>(M_DIM, G3H, H_DIM, Hb, W1, b1, G);
    qrnn_act_kernel<<<grid_act, blk>>>(G);
    qrnn_scan_kernel<<<grid_scan, blk>>>(G, Hb);

    // FC head
    sgemm_bias_kernel<<<grid_fc, blk>>>(M_DIM, OUT_DIM, H_DIM, Hb, Wfc, bfc, out);
}

// round 2
// speedup vs baseline: 3.8985x; 3.8985x over previous
#include <cuda_runtime.h>
#include <cuda_bf16.h>
#include <math.h>
#include <stdint.h>

// Problem dims (fixed)
#define T_DIM   512
#define B_DIM   64
#define IN_DIM  512
#define H_DIM   1024
#define OUT_DIM 512
#define M_DIM   (T_DIM * B_DIM)   // 32768
#define G3H     (3 * H_DIM)       // 3072

// ---------------------------------------------------------------------------
// Static device scratch (no runtime allocation)
// ---------------------------------------------------------------------------
__device__ float         g_G [(size_t)M_DIM * G3H];      // gate buffer fp32
__device__ __nv_bfloat16 g_xh[(size_t)M_DIM * IN_DIM];
__device__ __nv_bfloat16 g_xl[(size_t)M_DIM * IN_DIM];
__device__ __nv_bfloat16 g_Hh[(size_t)M_DIM * H_DIM];
__device__ __nv_bfloat16 g_Hl[(size_t)M_DIM * H_DIM];
__device__ __nv_bfloat16 g_W0h[IN_DIM * G3H],  g_W0l[IN_DIM * G3H];
__device__ __nv_bfloat16 g_W1h[H_DIM * G3H],   g_W1l[H_DIM * G3H];
__device__ __nv_bfloat16 g_Wfh[H_DIM * OUT_DIM], g_Wfl[H_DIM * OUT_DIM];

// ---------------------------------------------------------------------------
// PTX helpers
// ---------------------------------------------------------------------------
__device__ __forceinline__ uint32_t smem_u32(const void* p) {
    return (uint32_t)__cvta_generic_to_shared(p);
}

__device__ __forceinline__ void cp_async16(uint32_t saddr, const void* g) {
    asm volatile("cp.async.cg.shared.global [%0], [%1], 16;\n" :: "r"(saddr), "l"(g));
}
__device__ __forceinline__ void cp_commit() {
    asm volatile("cp.async.commit_group;\n");
}
template<int N> __device__ __forceinline__ void cp_wait() {
    asm volatile("cp.async.wait_group %0;\n" :: "n"(N));
}

__device__ __forceinline__ void ldmx4(uint32_t* r, uint32_t addr) {
    asm volatile("ldmatrix.sync.aligned.m8n8.x4.shared.b16 {%0,%1,%2,%3}, [%4];\n"
                 : "=r"(r[0]), "=r"(r[1]), "=r"(r[2]), "=r"(r[3]) : "r"(addr));
}
__device__ __forceinline__ void ldmx4t(uint32_t* r, uint32_t addr) {
    asm volatile("ldmatrix.sync.aligned.m8n8.x4.trans.shared.b16 {%0,%1,%2,%3}, [%4];\n"
                 : "=r"(r[0]), "=r"(r[1]), "=r"(r[2]), "=r"(r[3]) : "r"(addr));
}
__device__ __forceinline__ void mma16816(float* d, const uint32_t* a,
                                         uint32_t b0, uint32_t b1) {
    asm volatile(
        "mma.sync.aligned.m16n8k16.row.col.f32.bf16.bf16.f32 "
        "{%0,%1,%2,%3}, {%4,%5,%6,%7}, {%8,%9}, {%0,%1,%2,%3};\n"
        : "+f"(d[0]), "+f"(d[1]), "+f"(d[2]), "+f"(d[3])
        : "r"(a[0]), "r"(a[1]), "r"(a[2]), "r"(a[3]), "r"(b0), "r"(b1));
}

// ---------------------------------------------------------------------------
// Split-precision bf16x3 GEMM: C = Ah@Bh + Al@Bh + Ah@Bl + bias
// A: MxK row-major (bf16 hi/lo), B: KxN row-major (bf16 hi/lo), C fp32.
// 128x128x32 CTA tile, 8 warps (4M x 2N), warp tile 32x64, cp.async 2-stage.
// M%128==0, N%128==0, K%32==0 (holds for all calls).
// ---------------------------------------------------------------------------
#define STAGE_BYTES 32768   // 4 matrices * 8KB
// stage layout: [Ah 8K][Al 8K][Bh 8K][Bl 8K]

__global__ __launch_bounds__(256)
void gemm3_bf16_kernel(int M, int N, int K,
                       const __nv_bfloat16* __restrict__ Ah,
                       const __nv_bfloat16* __restrict__ Al,
                       const __nv_bfloat16* __restrict__ Bh,
                       const __nv_bfloat16* __restrict__ Bl,
                       const float* __restrict__ bias,
                       float* __restrict__ C)
{
    extern __shared__ char smem[];
    const uint32_t sbase = smem_u32(smem);

    const int tid    = threadIdx.x;
    const int lane   = tid & 31;
    const int warpId = tid >> 5;
    const int warpM  = warpId & 3;     // 0..3  -> rows warpM*32
    const int warpN  = warpId >> 2;    // 0..1  -> cols warpN*64

    const int rowBase = blockIdx.y * 128;
    const int colBase = blockIdx.x * 128;

    float acc[2][8][4];
    #pragma unroll
    for (int g = 0; g < 2; g++)
        #pragma unroll
        for (int n = 0; n < 8; n++)
            #pragma unroll
            for (int q = 0; q < 4; q++) acc[g][n][q] = 0.f;

    // ---- stage loader (cp.async) ----
    auto load_stage = [&](int s, int k0) {
        const uint32_t st = sbase + s * STAGE_BYTES;
        // A tiles: 128x32 bf16 = 512 x 16B chunks each (hi, lo)
        #pragma unroll
        for (int i = 0; i < 2; i++) {
            const int ch  = tid + i * 256;
            const int row = ch >> 2;
            const int c   = ch & 3;
            const uint32_t soff = row * 64 + ((c ^ ((row >> 1) & 3)) << 4);
            const size_t goff = (size_t)(rowBase + row) * K + k0 + c * 8;
            cp_async16(st + soff,          Ah + goff);
            cp_async16(st + 8192 + soff,   Al + goff);
        }
        // B tiles: 32x128 bf16 = 512 x 16B chunks each (hi, lo)
        #pragma unroll
        for (int i = 0; i < 2; i++) {
            const int ch  = tid + i * 256;
            const int row = ch >> 4;
            const int c   = ch & 15;
            const uint32_t soff = row * 256 + ((c ^ (row & 7)) << 4);
            const size_t goff = (size_t)(k0 + row) * N + colBase + c * 8;
            cp_async16(st + 16384 + soff,  Bh + goff);
            cp_async16(st + 24576 + soff,  Bl + goff);
        }
        cp_commit();
    };

    // ---- compute one stage (BK=32 -> 2 k16 steps) ----
    auto compute_stage = [&](int s) {
        const uint32_t aH = sbase + s * STAGE_BYTES;
        const uint32_t aL = aH + 8192;
        const uint32_t bH = aH + 16384;
        const uint32_t bL = aH + 24576;

        #pragma unroll
        for (int ks = 0; ks < 2; ks++) {
            uint32_t ah[2][4], al[2][4];
            #pragma unroll
            for (int g = 0; g < 2; g++) {
                const int row = warpM * 32 + g * 16 + (lane & 15);
                const int cb  = ks * 2 + (lane >> 4);
                const int sc  = cb ^ ((row >> 1) & 3);
                const uint32_t off = row * 64 + sc * 16;
                ldmx4(ah[g], aH + off);
                ldmx4(al[g], aL + off);
            }
            #pragma unroll
            for (int j = 0; j < 4; j++) {
                const int row = ks * 16 + (lane & 15);
                const int cb  = warpN * 8 + j * 2 + (lane >> 4);
                const int sc  = cb ^ (row & 7);
                const uint32_t off = row * 256 + sc * 16;
                uint32_t bh[4], bl[4];
                ldmx4t(bh, bH + off);
                ldmx4t(bl, bL + off);
                #pragma unroll
                for (int g = 0; g < 2; g++) {
                    mma16816(acc[g][2*j],   ah[g], bh[0], bh[1]);
                    mma16816(acc[g][2*j],   al[g], bh[0], bh[1]);
                    mma16816(acc[g][2*j],   ah[g], bl[0], bl[1]);
                    mma16816(acc[g][2*j+1], ah[g], bh[2], bh[3]);
                    mma16816(acc[g][2*j+1], al[g], bh[2], bh[3]);
                    mma16816(acc[g][2*j+1], ah[g], bl[2], bl[3]);
                }
            }
        }
    };

    const int KT = K >> 5;    // K / 32
    load_stage(0, 0);
    for (int kt = 0; kt < KT; kt++) {
        if (kt + 1 < KT) { load_stage((kt + 1) & 1, (kt + 1) * 32); cp_wait<1>(); }
        else             { cp_wait<0>(); }
        __syncthreads();
        compute_stage(kt & 1);
        __syncthreads();
    }

    // ---- epilogue: +bias, float2 stores ----
    #pragma unroll
    for (int g = 0; g < 2; g++) {
        const int r0 = rowBase + warpM * 32 + g * 16 + (lane >> 2);
        #pragma unroll
        for (int n = 0; n < 8; n++) {
            const int col = colBase + warpN * 64 + n * 8 + (lane & 3) * 2;
            const float b0 = __ldg(bias + col);
            const float b1 = __ldg(bias + col + 1);
            float2 v0 = make_float2(acc[g][n][0] + b0, acc[g][n][1] + b1);
            float2 v1 = make_float2(acc[g][n][2] + b0, acc[g][n][3] + b1);
            *(float2*)(C + (size_t)r0 * N + col)       = v0;
            *(float2*)(C + (size_t)(r0 + 8) * N + col) = v1;
        }
    }
}

// ---------------------------------------------------------------------------
// fp32 -> bf16 hi/lo split (for x and the weights)
// ---------------------------------------------------------------------------
__global__ void split_kernel(const float* __restrict__ X,
                             __nv_bfloat16* __restrict__ Xh,
                             __nv_bfloat16* __restrict__ Xl, int n)
{
    int i = blockIdx.x * blockDim.x + threadIdx.x;
    if (i >= n) return;
    float v = X[i];
    __nv_bfloat16 h = __float2bfloat16(v);
    Xh[i] = h;
    Xl[i] = __float2bfloat16(v - __bfloat162float(h));
}

// ---------------------------------------------------------------------------
// Activation: in-place on G (M x 3H):
//   z <- (1 - sigmoid(f)) * tanh(z)   (scan additive term)
//   f <- sigmoid(f) ;  o <- sigmoid(o)
// ---------------------------------------------------------------------------
__device__ __forceinline__ float sigmoidf_(float x) {
    return 1.0f / (1.0f + expf(-x));
}

__global__ void qrnn_act_kernel(float* __restrict__ G)
{
    const int HV = H_DIM / 4;
    int v = blockIdx.x * blockDim.x + threadIdx.x;
    if (v >= M_DIM * HV) return;
    const int m  = v / HV;
    const int hv = v % HV;
    const size_t base = (size_t)m * G3H + (size_t)hv * 4;

    float4 z = *(float4*)(G + base);
    float4 f = *(float4*)(G + base + H_DIM);
    float4 o = *(float4*)(G + base + 2 * H_DIM);

    float4 fs, a, os;
    fs.x = sigmoidf_(f.x); fs.y = sigmoidf_(f.y);
    fs.z = sigmoidf_(f.z); fs.w = sigmoidf_(f.w);
    a.x = (1.0f - fs.x) * tanhf(z.x);
    a.y = (1.0f - fs.y) * tanhf(z.y);
    a.z = (1.0f - fs.z) * tanhf(z.z);
    a.w = (1.0f - fs.w) * tanhf(z.w);
    os.x = sigmoidf_(o.x); os.y = sigmoidf_(o.y);
    os.z = sigmoidf_(o.z); os.w = sigmoidf_(o.w);

    *(float4*)(G + base)             = a;
    *(float4*)(G + base + H_DIM)     = fs;
    *(float4*)(G + base + 2 * H_DIM) = os;
}

// ---------------------------------------------------------------------------
// fo-pool scan + fused bf16 hi/lo split of the layer output:
//   c_t = f_t * c + a_t ;  v = o_t * c_t ; Hh/Hl <- split(v)
// ---------------------------------------------------------------------------
__global__ void qrnn_scan_kernel(const float* __restrict__ G,
                                 __nv_bfloat16* __restrict__ Hh,
                                 __nv_bfloat16* __restrict__ Hl)
{
    const int idx = blockIdx.x * blockDim.x + threadIdx.x;
    if (idx >= B_DIM * H_DIM) return;
    const int b = idx / H_DIM;
    const int h = idx % H_DIM;

    float c = 0.0f;
    #pragma unroll 4
    for (int t = 0; t < T_DIM; t++) {
        const size_t base = ((size_t)t * B_DIM + b) * G3H + h;
        const float a = G[base];
        const float f = G[base + H_DIM];
        const float o = G[base + 2 * H_DIM];
        c = fmaf(f, c, a);
        const float v = o * c;
        __nv_bfloat16 hi = __float2bfloat16(v);
        const size_t oidx = ((size_t)t * B_DIM + b) * H_DIM + h;
        Hh[oidx] = hi;
        Hl[oidx] = __float2bfloat16(v - __bfloat162float(hi));
    }
}

// ---------------------------------------------------------------------------
// Launch
// ---------------------------------------------------------------------------
extern "C" void kernel_launch(void* const* d_in, const int* in_sizes, int n_in,
                              void* d_out, int out_size)
{
    const float* x   = (const float*)d_in[0];
    const float* W0  = (const float*)d_in[1];
    const float* b0  = (const float*)d_in[2];
    const float* W1  = (const float*)d_in[3];
    const float* b1  = (const float*)d_in[4];
    const float* Wfc = (const float*)d_in[5];
    const float* bfc = (const float*)d_in[6];
    float* out = (float*)d_out;

    float *G;
    __nv_bfloat16 *xh, *xl, *Hh, *Hl, *W0h, *W0l, *W1h, *W1l, *Wfh, *Wfl;
    cudaGetSymbolAddress((void**)&G,   g_G);
    cudaGetSymbolAddress((void**)&xh,  g_xh);
    cudaGetSymbolAddress((void**)&xl,  g_xl);
    cudaGetSymbolAddress((void**)&Hh,  g_Hh);
    cudaGetSymbolAddress((void**)&Hl,  g_Hl);
    cudaGetSymbolAddress((void**)&W0h, g_W0h);
    cudaGetSymbolAddress((void**)&W0l, g_W0l);
    cudaGetSymbolAddress((void**)&W1h, g_W1h);
    cudaGetSymbolAddress((void**)&W1l, g_W1l);
    cudaGetSymbolAddress((void**)&Wfh, g_Wfh);
    cudaGetSymbolAddress((void**)&Wfl, g_Wfl);

    static bool attr_done = false;
    if (!attr_done) {
        cudaFuncSetAttribute(gemm3_bf16_kernel,
                             cudaFuncAttributeMaxDynamicSharedMemorySize,
                             2 * STAGE_BYTES);
        attr_done = true;
    }

    dim3 blk(256);
    dim3 grid_g(G3H / 128, M_DIM / 128);     // 24 x 256
    dim3 grid_fc(OUT_DIM / 128, M_DIM / 128);// 4 x 256
    const int actThreads = M_DIM * (H_DIM / 4);
    dim3 grid_act((actThreads + 255) / 256);
    dim3 grid_scan((B_DIM * H_DIM + 255) / 256);

    // Splits (every call; deterministic)
    {
        int n;
        n = M_DIM * IN_DIM;   split_kernel<<<(n+255)/256, blk>>>(x,   xh,  xl,  n);
        n = IN_DIM * G3H;     split_kernel<<<(n+255)/256, blk>>>(W0,  W0h, W0l, n);
        n = H_DIM * G3H;      split_kernel<<<(n+255)/256, blk>>>(W1,  W1h, W1l, n);
        n = H_DIM * OUT_DIM;  split_kernel<<<(n+255)/256, blk>>>(Wfc, Wfh, Wfl, n);
    }

    // Layer 0
    gemm3_bf16_kernel<<<grid_g, blk, 2*STAGE_BYTES>>>(M_DIM, G3H, IN_DIM,
                                                      xh, xl, W0h, W0l, b0, G);
    qrnn_act_kernel<<<grid_act, blk>>>(G);
    qrnn_scan_kernel<<<grid_scan, blk>>>(G, Hh, Hl);

    // Layer 1
    gemm3_bf16_kernel<<<grid_g, blk, 2*STAGE_BYTES>>>(M_DIM, G3H, H_DIM,
                                                      Hh, Hl, W1h, W1l, b1, G);
    qrnn_act_kernel<<<grid_act, blk>>>(G);
    qrnn_scan_kernel<<<grid_scan, blk>>>(G, Hh, Hl);

    // FC head
    gemm3_bf16_kernel<<<grid_fc, blk, 2*STAGE_BYTES>>>(M_DIM, OUT_DIM, H_DIM,
                                                       Hh, Hl, Wfh, Wfl, bfc, out);
}

// round 4
// speedup vs baseline: 4.1104x; 1.0544x over previous
#include <cuda_runtime.h>
#include <cuda_bf16.h>
#include <math.h>
#include <stdint.h>

// Problem dims (fixed)
#define T_DIM   512
#define B_DIM   64
#define IN_DIM  512
#define H_DIM   1024
#define OUT_DIM 512
#define M_DIM   (T_DIM * B_DIM)   // 32768
#define G3H     (3 * H_DIM)       // 3072

// ---------------------------------------------------------------------------
// Static device scratch
// ---------------------------------------------------------------------------
__device__ float         g_G [(size_t)M_DIM * G3H];      // post-act gates fp32
__device__ __nv_bfloat16 g_xh[(size_t)M_DIM * IN_DIM];
__device__ __nv_bfloat16 g_xl[(size_t)M_DIM * IN_DIM];
__device__ __nv_bfloat16 g_Hh[(size_t)M_DIM * H_DIM];
__device__ __nv_bfloat16 g_Hl[(size_t)M_DIM * H_DIM];
__device__ __nv_bfloat16 g_W0h[IN_DIM * G3H],  g_W0l[IN_DIM * G3H];
__device__ __nv_bfloat16 g_W1h[H_DIM * G3H],   g_W1l[H_DIM * G3H];
__device__ __nv_bfloat16 g_Wfh[H_DIM * OUT_DIM], g_Wfl[H_DIM * OUT_DIM];

// ---------------------------------------------------------------------------
// PTX helpers (Ampere-class async copy + ldmatrix + bf16 mma — all sm_103 ok)
// ---------------------------------------------------------------------------
__device__ __forceinline__ uint32_t smem_u32(const void* p) {
    return (uint32_t)__cvta_generic_to_shared(p);
}
__device__ __forceinline__ void cp_async16(uint32_t saddr, const void* g) {
    asm volatile("cp.async.cg.shared.global [%0], [%1], 16;\n" :: "r"(saddr), "l"(g));
}
__device__ __forceinline__ void cp_commit() {
    asm volatile("cp.async.commit_group;\n");
}
template<int N> __device__ __forceinline__ void cp_wait() {
    asm volatile("cp.async.wait_group %0;\n" :: "n"(N));
}
__device__ __forceinline__ void ldmx4(uint32_t* r, uint32_t addr) {
    asm volatile("ldmatrix.sync.aligned.m8n8.x4.shared.b16 {%0,%1,%2,%3}, [%4];\n"
                 : "=r"(r[0]), "=r"(r[1]), "=r"(r[2]), "=r"(r[3]) : "r"(addr));
}
__device__ __forceinline__ void ldmx4t(uint32_t* r, uint32_t addr) {
    asm volatile("ldmatrix.sync.aligned.m8n8.x4.trans.shared.b16 {%0,%1,%2,%3}, [%4];\n"
                 : "=r"(r[0]), "=r"(r[1]), "=r"(r[2]), "=r"(r[3]) : "r"(addr));
}
__device__ __forceinline__ void mma16816(float* d, const uint32_t* a,
                                         uint32_t b0, uint32_t b1) {
    asm volatile(
        "mma.sync.aligned.m16n8k16.row.col.f32.bf16.bf16.f32 "
        "{%0,%1,%2,%3}, {%4,%5,%6,%7}, {%8,%9}, {%0,%1,%2,%3};\n"
        : "+f"(d[0]), "+f"(d[1]), "+f"(d[2]), "+f"(d[3])
        : "r"(a[0]), "r"(a[1]), "r"(a[2]), "r"(a[3]), "r"(b0), "r"(b1));
}

// ---------------------------------------------------------------------------
// Split-precision bf16x3 GEMM with fused bias + activation epilogue.
//   C = act(Ah@Bh + Al@Bh + Ah@Bl + bias)
// 128x128x32 CTA tile, 8 warps (4M x 2N), warp tile 32x64, 3-stage cp.async.
// actMode: 0 = none (FC); 1 = gates (cols < H_DIM: tanh, else sigmoid).
// ---------------------------------------------------------------------------
#define STAGE_BYTES 32768     // [Ah 8K][Al 8K][Bh 8K][Bl 8K]
#define NSTAGE 3
#define GEMM_SMEM (NSTAGE * STAGE_BYTES)

__global__ __launch_bounds__(256)
void gemm3_bf16_kernel(int M, int N, int K,
                       const __nv_bfloat16* __restrict__ Ah,
                       const __nv_bfloat16* __restrict__ Al,
                       const __nv_bfloat16* __restrict__ Bh,
                       const __nv_bfloat16* __restrict__ Bl,
                       const float* __restrict__ bias,
                       float* __restrict__ C,
                       int actMode)
{
    extern __shared__ char smem[];
    const uint32_t sbase = smem_u32(smem);

    const int tid    = threadIdx.x;
    const int lane   = tid & 31;
    const int warpId = tid >> 5;
    const int warpM  = warpId & 3;
    const int warpN  = warpId >> 2;

    const int rowBase = blockIdx.y * 128;
    const int colBase = blockIdx.x * 128;

    float acc[2][8][4];
    #pragma unroll
    for (int g = 0; g < 2; g++)
        #pragma unroll
        for (int n = 0; n < 8; n++)
            #pragma unroll
            for (int q = 0; q < 4; q++) acc[g][n][q] = 0.f;

    auto load_stage = [&](int s, int k0) {
        const uint32_t st = sbase + s * STAGE_BYTES;
        #pragma unroll
        for (int i = 0; i < 2; i++) {
            const int ch  = tid + i * 256;
            const int row = ch >> 2;
            const int c   = ch & 3;
            const uint32_t soff = row * 64 + ((c ^ ((row >> 1) & 3)) << 4);
            const size_t goff = (size_t)(rowBase + row) * K + k0 + c * 8;
            cp_async16(st + soff,          Ah + goff);
            cp_async16(st + 8192 + soff,   Al + goff);
        }
        #pragma unroll
        for (int i = 0; i < 2; i++) {
            const int ch  = tid + i * 256;
            const int row = ch >> 4;
            const int c   = ch & 15;
            const uint32_t soff = row * 256 + ((c ^ (row & 7)) << 4);
            const size_t goff = (size_t)(k0 + row) * N + colBase + c * 8;
            cp_async16(st + 16384 + soff,  Bh + goff);
            cp_async16(st + 24576 + soff,  Bl + goff);
        }
        cp_commit();
    };

    auto compute_stage = [&](int s) {
        const uint32_t aH = sbase + s * STAGE_BYTES;
        const uint32_t aL = aH + 8192;
        const uint32_t bH = aH + 16384;
        const uint32_t bL = aH + 24576;

        #pragma unroll
        for (int ks = 0; ks < 2; ks++) {
            uint32_t ah[2][4], al[2][4];
            #pragma unroll
            for (int g = 0; g < 2; g++) {
                const int row = warpM * 32 + g * 16 + (lane & 15);
                const int cb  = ks * 2 + (lane >> 4);
                const int sc  = cb ^ ((row >> 1) & 3);
                const uint32_t off = row * 64 + sc * 16;
                ldmx4(ah[g], aH + off);
                ldmx4(al[g], aL + off);
            }
            #pragma unroll
            for (int j = 0; j < 4; j++) {
                const int row = ks * 16 + (lane & 15);
                const int cb  = warpN * 8 + j * 2 + (lane >> 4);
                const int sc  = cb ^ (row & 7);
                const uint32_t off = row * 256 + sc * 16;
                uint32_t bh[4], bl[4];
                ldmx4t(bh, bH + off);
                ldmx4t(bl, bL + off);
                #pragma unroll
                for (int g = 0; g < 2; g++) {
                    mma16816(acc[g][2*j],   ah[g], bh[0], bh[1]);
                    mma16816(acc[g][2*j],   al[g], bh[0], bh[1]);
                    mma16816(acc[g][2*j],   ah[g], bl[0], bl[1]);
                    mma16816(acc[g][2*j+1], ah[g], bh[2], bh[3]);
                    mma16816(acc[g][2*j+1], al[g], bh[2], bh[3]);
                    mma16816(acc[g][2*j+1], ah[g], bl[2], bl[3]);
                }
            }
        }
    };

    const int KT = K >> 5;   // >= 16 always
    load_stage(0, 0);
    load_stage(1, 32);

    for (int kt = 0; kt < KT; kt++) {
        cp_wait<1>();
        __syncthreads();
        compute_stage(kt % 3);
        if (kt + 2 < KT) load_stage((kt + 2) % 3, (kt + 2) * 32);
        else             cp_commit();      // empty group keeps counting uniform
    }

    // ---- fused epilogue: +bias, activation, store ----
    const int doTanh = (actMode == 1) && (colBase < H_DIM);
    const int doSig  = (actMode == 1) && (colBase >= H_DIM);

    #pragma unroll
    for (int g = 0; g < 2; g++) {
        const int r0 = rowBase + warpM * 32 + g * 16 + (lane >> 2);
        #pragma unroll
        for (int n = 0; n < 8; n++) {
            const int col = colBase + warpN * 64 + n * 8 + (lane & 3) * 2;
            const float b0 = __ldg(bias + col);
            const float b1 = __ldg(bias + col + 1);
            float v[4] = { acc[g][n][0] + b0, acc[g][n][1] + b1,
                           acc[g][n][2] + b0, acc[g][n][3] + b1 };
            if (doTanh) {
                #pragma unroll
                for (int q = 0; q < 4; q++)
                    v[q] = 1.0f - __fdividef(2.0f, __expf(2.0f * v[q]) + 1.0f);
            } else if (doSig) {
                #pragma unroll
                for (int q = 0; q < 4; q++)
                    v[q] = __fdividef(1.0f, 1.0f + __expf(-v[q]));
            }
            *(float2*)(C + (size_t)r0 * N + col)       = make_float2(v[0], v[1]);
            *(float2*)(C + (size_t)(r0 + 8) * N + col) = make_float2(v[2], v[3]);
        }
    }
}

// ---------------------------------------------------------------------------
// fp32 -> bf16 hi/lo split (row-major)
// ---------------------------------------------------------------------------
__global__ void split_kernel(const float* __restrict__ X,
                             __nv_bfloat16* __restrict__ Xh,
                             __nv_bfloat16* __restrict__ Xl, int n)
{
    int i = blockIdx.x * blockDim.x + threadIdx.x;
    if (i >= n) return;
    float v = X[i];
    __nv_bfloat16 h = __float2bfloat16(v);
    Xh[i] = h;
    Xl[i] = __float2bfloat16(v - __bfloat162float(h));
}

// ---------------------------------------------------------------------------
// fo-pool scan. G holds post-act gates: z'=tanh(z), f'=sigmoid(f), o'=sigmoid(o)
//   c = f'*c + (1-f')*z' = fma(f', c - z', z') ;  v = o'*c -> bf16 hi/lo
// ---------------------------------------------------------------------------
__global__ void qrnn_scan_kernel(const float* __restrict__ G,
                                 __nv_bfloat16* __restrict__ Hh,
                                 __nv_bfloat16* __restrict__ Hl)
{
    const int idx = blockIdx.x * blockDim.x + threadIdx.x;
    if (idx >= B_DIM * H_DIM) return;
    const int b = idx / H_DIM;
    const int h = idx % H_DIM;

    float c = 0.0f;
    #pragma unroll 4
    for (int t = 0; t < T_DIM; t++) {
        const size_t base = ((size_t)t * B_DIM + b) * G3H + h;
        const float z = G[base];
        const float f = G[base + H_DIM];
        const float o = G[base + 2 * H_DIM];
        c = fmaf(f, c - z, z);
        const float v = o * c;
        __nv_bfloat16 hi = __float2bfloat16(v);
        const size_t oidx = ((size_t)t * B_DIM + b) * H_DIM + h;
        Hh[oidx] = hi;
        Hl[oidx] = __float2bfloat16(v - __bfloat162float(hi));
    }
}

// ---------------------------------------------------------------------------
// Launch
// ---------------------------------------------------------------------------
extern "C" void kernel_launch(void* const* d_in, const int* in_sizes, int n_in,
                              void* d_out, int out_size)
{
    const float* x   = (const float*)d_in[0];
    const float* W0  = (const float*)d_in[1];
    const float* b0  = (const float*)d_in[2];
    const float* W1  = (const float*)d_in[3];
    const float* b1  = (const float*)d_in[4];
    const float* Wfc = (const float*)d_in[5];
    const float* bfc = (const float*)d_in[6];
    float* out = (float*)d_out;

    float *G;
    __nv_bfloat16 *xh, *xl, *Hh, *Hl, *W0h, *W0l, *W1h, *W1l, *Wfh, *Wfl;
    cudaGetSymbolAddress((void**)&G,   g_G);
    cudaGetSymbolAddress((void**)&xh,  g_xh);
    cudaGetSymbolAddress((void**)&xl,  g_xl);
    cudaGetSymbolAddress((void**)&Hh,  g_Hh);
    cudaGetSymbolAddress((void**)&Hl,  g_Hl);
    cudaGetSymbolAddress((void**)&W0h, g_W0h);
    cudaGetSymbolAddress((void**)&W0l, g_W0l);
    cudaGetSymbolAddress((void**)&W1h, g_W1h);
    cudaGetSymbolAddress((void**)&W1l, g_W1l);
    cudaGetSymbolAddress((void**)&Wfh, g_Wfh);
    cudaGetSymbolAddress((void**)&Wfl, g_Wfl);

    static bool attr_done = false;
    if (!attr_done) {
        cudaFuncSetAttribute(gemm3_bf16_kernel,
                             cudaFuncAttributeMaxDynamicSharedMemorySize,
                             GEMM_SMEM);
        attr_done = true;
    }

    dim3 blk(256);
    dim3 grid_g(G3H / 128, M_DIM / 128);      // 24 x 256
    dim3 grid_fc(OUT_DIM / 128, M_DIM / 128); // 4 x 256
    dim3 grid_scan((B_DIM * H_DIM + 255) / 256);

    // Splits
    {
        int n;
        n = M_DIM * IN_DIM;   split_kernel<<<(n+255)/256, blk>>>(x,   xh,  xl,  n);
        n = IN_DIM * G3H;     split_kernel<<<(n+255)/256, blk>>>(W0,  W0h, W0l, n);
        n = H_DIM * G3H;      split_kernel<<<(n+255)/256, blk>>>(W1,  W1h, W1l, n);
        n = H_DIM * OUT_DIM;  split_kernel<<<(n+255)/256, blk>>>(Wfc, Wfh, Wfl, n);
    }

    // Layer 0: GEMM (+fused act) -> scan
    gemm3_bf16_kernel<<<grid_g, blk, GEMM_SMEM>>>(M_DIM, G3H, IN_DIM,
                                                  xh, xl, W0h, W0l, b0, G, 1);
    qrnn_scan_kernel<<<grid_scan, blk>>>(G, Hh, Hl);

    // Layer 1
    gemm3_bf16_kernel<<<grid_g, blk, GEMM_SMEM>>>(M_DIM, G3H, H_DIM,
                                                  Hh, Hl, W1h, W1l, b1, G, 1);
    qrnn_scan_kernel<<<grid_scan, blk>>>(G, Hh, Hl);

    // FC head (no act)
    gemm3_bf16_kernel<<<grid_fc, blk, GEMM_SMEM>>>(M_DIM, OUT_DIM, H_DIM,
                                                   Hh, Hl, Wfh, Wfl, bfc, out, 0);
}